// round 7
// baseline (speedup 1.0000x reference)
#include <cuda_runtime.h>

namespace {
constexpr int W = 512, H = 512, OW = 506, OH = 506, CH = 96;
constexpr int NB = 16;                 // bands per channel
constexpr int BH = 32;                 // output rows per band (last: 26)
constexpr int NWARPS = CH * NB;        // 1536 independent warps

constexpr float C1f = 0.01f * 0.01f;
constexpr float C2f = 0.03f * 0.03f;
constexpr float INV  = 1.0f / 49.0f;
constexpr float INV2 = INV * INV;
constexpr float COV  = 49.0f / 48.0f;
constexpr float kA  = 2.0f * INV2;
constexpr float kC  = INV2;
constexpr float kB1 = 2.0f * COV * INV;
constexpr float kB2 = 2.0f * COV * INV2;
constexpr float kD1 = COV * INV;       // D = kD1*Szz - kD2*Q + C2, Szz = Sxx+Syy
constexpr float kD2 = COV * INV2;
}

using u64 = unsigned long long;

// f32x2 packed helpers (sm_103a dual-fp32 per instruction)
__device__ __forceinline__ u64 pk2(float lo, float hi) {
    u64 r; asm("mov.b64 %0, {%1, %2};" : "=l"(r) : "f"(lo), "f"(hi)); return r;
}
__device__ __forceinline__ void upk2(u64 v, float& lo, float& hi) {
    asm("mov.b64 {%0, %1}, %2;" : "=f"(lo), "=f"(hi) : "l"(v));
}
__device__ __forceinline__ u64 add2(u64 a, u64 b) {
    u64 d; asm("add.rn.f32x2 %0, %1, %2;" : "=l"(d) : "l"(a), "l"(b)); return d;
}
__device__ __forceinline__ u64 mul2(u64 a, u64 b) {
    u64 d; asm("mul.rn.f32x2 %0, %1, %2;" : "=l"(d) : "l"(a), "l"(b)); return d;
}
__device__ __forceinline__ u64 fma2(u64 a, u64 b, u64 c) {
    u64 d; asm("fma.rn.f32x2 %0, %1, %2, %3;" : "=l"(d) : "l"(a), "l"(b), "l"(c)); return d;
}

__device__ double g_partials[NWARPS];
__device__ unsigned int g_count = 0;

__global__ __launch_bounds__(32, 10) void ssim_warp(const float* __restrict__ X,
                                                    const float* __restrict__ Y,
                                                    float* __restrict__ out) {
    const int wid = blockIdx.x;
    const int ch = wid >> 4;
    const int band = wid & (NB - 1);
    const int lane = threadIdx.x;
    const float* __restrict__ x = X + (size_t)ch * H * W;
    const float* __restrict__ y = Y + (size_t)ch * H * W;
    const int r0 = band * BH;
    const int rEnd = min(r0 + BH, OH);
    const int colbase = 8 * lane;      // group g covers cols 256g + 8*lane .. +7

    const u64 NEG1 = pk2(-1.0f, -1.0f);

    // packed vertical column sums: quantity q, pair p = 4g + j  (cols 8g+2j, 8g+2j+1)
    u64 sp[4][8];
#pragma unroll
    for (int q = 0; q < 4; q++)
#pragma unroll
        for (int p = 0; p < 8; p++) sp[q][p] = 0ull;

    // prologue: accumulate 7 input rows (packed f32x2)
#pragma unroll
    for (int rr = 0; rr < 7; rr++) {
        const size_t base = (size_t)(r0 + rr) * W + colbase;
#pragma unroll
        for (int g = 0; g < 2; g++) {
            const float4 a0 = *(const float4*)(x + base + 256 * g);
            const float4 a1 = *(const float4*)(x + base + 256 * g + 4);
            const float4 b0 = *(const float4*)(y + base + 256 * g);
            const float4 b1 = *(const float4*)(y + base + 256 * g + 4);
            const u64 xp[4] = {pk2(a0.x, a0.y), pk2(a0.z, a0.w),
                               pk2(a1.x, a1.y), pk2(a1.z, a1.w)};
            const u64 yp[4] = {pk2(b0.x, b0.y), pk2(b0.z, b0.w),
                               pk2(b1.x, b1.y), pk2(b1.z, b1.w)};
#pragma unroll
            for (int j = 0; j < 4; j++) {
                const int p = 4 * g + j;
                sp[0][p] = add2(sp[0][p], xp[j]);
                sp[1][p] = add2(sp[1][p], yp[j]);
                sp[2][p] = fma2(xp[j], xp[j], sp[2][p]);
                sp[2][p] = fma2(yp[j], yp[j], sp[2][p]);
                sp[3][p] = fma2(xp[j], yp[j], sp[3][p]);
            }
        }
    }

    float acc = 0.0f;

    // prefetch buffer for next iteration's rows (r+6 new, r-1 old)
    float4 pxn[2][2], pyn[2][2], pxo[2][2], pyo[2][2];

#define LOADP(rr)                                                             \
    {                                                                         \
        const size_t rn_ = (size_t)((rr) + 6) * W + colbase;                  \
        const size_t ro_ = (size_t)((rr) - 1) * W + colbase;                  \
        _Pragma("unroll")                                                     \
        for (int g = 0; g < 2; g++) {                                         \
            pxn[g][0] = *(const float4*)(x + rn_ + 256 * g);                  \
            pxn[g][1] = *(const float4*)(x + rn_ + 256 * g + 4);              \
            pyn[g][0] = *(const float4*)(y + rn_ + 256 * g);                  \
            pyn[g][1] = *(const float4*)(y + rn_ + 256 * g + 4);              \
            pxo[g][0] = *(const float4*)(x + ro_ + 256 * g);                  \
            pxo[g][1] = *(const float4*)(x + ro_ + 256 * g + 4);              \
            pyo[g][0] = *(const float4*)(y + ro_ + 256 * g);                  \
            pyo[g][1] = *(const float4*)(y + ro_ + 256 * g + 4);              \
        }                                                                     \
    }

#define CONSUME()                                                             \
    {                                                                         \
        _Pragma("unroll")                                                     \
        for (int g = 0; g < 2; g++) {                                         \
            const u64 xn2[4] = {pk2(pxn[g][0].x, pxn[g][0].y),                \
                                pk2(pxn[g][0].z, pxn[g][0].w),                \
                                pk2(pxn[g][1].x, pxn[g][1].y),                \
                                pk2(pxn[g][1].z, pxn[g][1].w)};               \
            const u64 yn2[4] = {pk2(pyn[g][0].x, pyn[g][0].y),                \
                                pk2(pyn[g][0].z, pyn[g][0].w),                \
                                pk2(pyn[g][1].x, pyn[g][1].y),                \
                                pk2(pyn[g][1].z, pyn[g][1].w)};               \
            const u64 xo2[4] = {pk2(pxo[g][0].x, pxo[g][0].y),                \
                                pk2(pxo[g][0].z, pxo[g][0].w),                \
                                pk2(pxo[g][1].x, pxo[g][1].y),                \
                                pk2(pxo[g][1].z, pxo[g][1].w)};               \
            const u64 yo2[4] = {pk2(pyo[g][0].x, pyo[g][0].y),                \
                                pk2(pyo[g][0].z, pyo[g][0].w),                \
                                pk2(pyo[g][1].x, pyo[g][1].y),                \
                                pk2(pyo[g][1].z, pyo[g][1].w)};               \
            _Pragma("unroll")                                                 \
            for (int j = 0; j < 4; j++) {                                     \
                const int p = 4 * g + j;                                      \
                u64 t = fma2(xo2[j], NEG1, xn2[j]);                           \
                sp[0][p] = add2(sp[0][p], t);                                 \
                u64 u = fma2(yo2[j], NEG1, yn2[j]);                           \
                sp[1][p] = add2(sp[1][p], u);                                 \
                u64 v = mul2(xo2[j], xo2[j]);                                 \
                v = fma2(yo2[j], yo2[j], v);                                  \
                sp[2][p] = fma2(xn2[j], xn2[j], sp[2][p]);                    \
                sp[2][p] = fma2(yn2[j], yn2[j], sp[2][p]);                    \
                sp[2][p] = fma2(v, NEG1, sp[2][p]);                           \
                u64 m = mul2(xo2[j], yo2[j]);                                 \
                sp[3][p] = fma2(xn2[j], yn2[j], sp[3][p]);                    \
                sp[3][p] = fma2(m, NEG1, sp[3][p]);                           \
            }                                                                 \
        }                                                                     \
    }

    // horizontal 7-windows via own prefix sums + 6 shuffled neighbor prefixes
#define PROCESS_ROW()                                                         \
    {                                                                         \
        _Pragma("unroll")                                                     \
        for (int g = 0; g < 2; g++) {                                         \
            float w[4][8];                                                    \
            _Pragma("unroll")                                                 \
            for (int q = 0; q < 4; q++) {                                     \
                float e0, e1, e2, e3, e4, e5, e6, e7;                         \
                upk2(sp[q][4 * g + 0], e0, e1);                               \
                upk2(sp[q][4 * g + 1], e2, e3);                               \
                upk2(sp[q][4 * g + 2], e4, e5);                               \
                upk2(sp[q][4 * g + 3], e6, e7);                               \
                float P[8];                                                   \
                P[0] = e0; P[1] = P[0] + e1; P[2] = P[1] + e2;                \
                P[3] = P[2] + e3; P[4] = P[3] + e4; P[5] = P[4] + e5;         \
                P[6] = P[5] + e6; P[7] = P[6] + e7;                           \
                float pub[6];                                                 \
                if (g == 0) {                                                 \
                    /* lane0 publishes its group-1 prefixes for the wrap */   \
                    float f0, f1, f2, f3, f4, f5;                             \
                    upk2(sp[q][4], f0, f1);                                   \
                    upk2(sp[q][5], f2, f3);                                   \
                    upk2(sp[q][6], f4, f5);                                   \
                    const float a0 = f0, a1 = a0 + f1, a2 = a1 + f2;          \
                    const float a3 = a2 + f3, a4 = a3 + f4, a5 = a4 + f5;     \
                    const bool z = (lane == 0);                               \
                    pub[0] = z ? a0 : P[0]; pub[1] = z ? a1 : P[1];           \
                    pub[2] = z ? a2 : P[2]; pub[3] = z ? a3 : P[3];           \
                    pub[4] = z ? a4 : P[4]; pub[5] = z ? a5 : P[5];           \
                } else {                                                      \
                    _Pragma("unroll")                                         \
                    for (int j = 0; j < 6; j++) pub[j] = P[j];                \
                }                                                             \
                float nP[6];                                                  \
                _Pragma("unroll")                                             \
                for (int j = 0; j < 6; j++)                                   \
                    nP[j] = __shfl_sync(0xffffffffu, pub[j], (lane + 1) & 31);\
                const float T = P[7];                                         \
                w[q][0] = P[6];                                               \
                w[q][1] = T - P[0];                                           \
                _Pragma("unroll")                                             \
                for (int i = 2; i < 8; i++)                                   \
                    w[q][i] = (T - P[i - 1]) + nP[i - 2];                     \
            }                                                                 \
            float num[8], den[8];                                             \
            _Pragma("unroll")                                                 \
            for (int k = 0; k < 8; k++) {                                     \
                const float Sx = w[0][k], Sy = w[1][k];                       \
                const float Szz = w[2][k], Sxy = w[3][k];                     \
                const float Pm = Sx * Sy;                                     \
                const float Q = fmaf(Sx, Sx, Sy * Sy);                        \
                const float A = fmaf(kA, Pm, C1f);                            \
                const float Cc = fmaf(kC, Q, C1f);                            \
                const float B = fmaf(kB1, Sxy, fmaf(-kB2, Pm, C2f));          \
                const float D = fmaf(kD1, Szz, fmaf(-kD2, Q, C2f));           \
                const bool valid = (g == 0) || (256 + colbase + k < OW);      \
                num[k] = valid ? A * B : 0.0f;                                \
                den[k] = valid ? Cc * D : 1.0f;                               \
            }                                                                 \
            /* one MUFU.RCP for 8 pixels */                                   \
            float pre[8];                                                     \
            pre[0] = 1.0f;                                                    \
            _Pragma("unroll")                                                 \
            for (int k = 1; k < 8; k++) pre[k] = pre[k - 1] * den[k - 1];     \
            const float tot = pre[7] * den[7];                                \
            const float rall = 1.0f / tot;                                    \
            float suf = 1.0f, contrib = 0.0f;                                 \
            _Pragma("unroll")                                                 \
            for (int k = 7; k >= 0; k--) {                                    \
                contrib = fmaf(num[k], pre[k] * suf, contrib);                \
                suf *= den[k];                                                \
            }                                                                 \
            acc = fmaf(contrib, rall, acc);                                   \
        }                                                                     \
    }

    // software-pipelined main loop: loads for iter r+1 issue before iter r's math
    LOADP(r0 + 1);
    PROCESS_ROW();     // row r0 (sums valid from prologue)

    for (int r = r0 + 1; r < rEnd; r++) {
        CONSUME();                       // fold prefetched rows into sums
        if (r + 1 < rEnd) LOADP(r + 1);  // issue next loads early (hide latency)
        PROCESS_ROW();                   // math overlaps in-flight loads
    }

#undef LOADP
#undef CONSUME
#undef PROCESS_ROW

    // warp tree-reduce (fixed order -> deterministic)
#pragma unroll
    for (int off = 16; off > 0; off >>= 1)
        acc += __shfl_down_sync(0xffffffffu, acc, off);

    int last = 0;
    if (lane == 0) {
        g_partials[wid] = (double)acc;
        __threadfence();
        const unsigned int c = atomicInc(&g_count, NWARPS - 1);  // wraps to 0
        last = (c == NWARPS - 1) ? 1 : 0;
    }
    last = __shfl_sync(0xffffffffu, last, 0);

    if (last) {
        const volatile double* vp = g_partials;
        double sd = 0.0;
        for (int i = lane; i < NWARPS; i += 32) sd += vp[i];
#pragma unroll
        for (int off = 16; off > 0; off >>= 1)
            sd += __shfl_down_sync(0xffffffffu, sd, off);
        if (lane == 0)
            out[0] = (float)(sd / ((double)CH * (double)OH * (double)OW));
    }
}

extern "C" void kernel_launch(void* const* d_in, const int* in_sizes, int n_in,
                              void* d_out, int out_size) {
    const float* x = (const float*)d_in[0];
    const float* y = (const float*)d_in[1];
    float* out = (float*)d_out;
    ssim_warp<<<NWARPS, 32>>>(x, y, out);
}

// round 8
// speedup vs baseline: 1.0611x; 1.0611x over previous
#include <cuda_runtime.h>

namespace {
constexpr int W = 512, H = 512, OW = 506, OH = 506, CH = 96;
constexpr int NB = 16;                 // bands per channel
constexpr int BH = 32;                 // output rows per band (last: 26)
constexpr int NWARPS = CH * NB * 2;    // 3072: two warps per band (column halves)

constexpr float C1f = 0.01f * 0.01f;
constexpr float C2f = 0.03f * 0.03f;
constexpr float INV  = 1.0f / 49.0f;
constexpr float INV2 = INV * INV;
constexpr float COV  = 49.0f / 48.0f;
constexpr float kA  = 2.0f * INV2;
constexpr float kC  = INV2;
constexpr float kB1 = 2.0f * COV * INV;
constexpr float kB2 = 2.0f * COV * INV2;
constexpr float kD1 = COV * INV;       // D = kD1*Szz - kD2*Q + C2, Szz = Sxx+Syy
constexpr float kD2 = COV * INV2;
}

using u64 = unsigned long long;

__device__ __forceinline__ u64 pk2(float lo, float hi) {
    u64 r; asm("mov.b64 %0, {%1, %2};" : "=l"(r) : "f"(lo), "f"(hi)); return r;
}
__device__ __forceinline__ void upk2(u64 v, float& lo, float& hi) {
    asm("mov.b64 {%0, %1}, %2;" : "=f"(lo), "=f"(hi) : "l"(v));
}
__device__ __forceinline__ u64 add2(u64 a, u64 b) {
    u64 d; asm("add.rn.f32x2 %0, %1, %2;" : "=l"(d) : "l"(a), "l"(b)); return d;
}
__device__ __forceinline__ u64 mul2(u64 a, u64 b) {
    u64 d; asm("mul.rn.f32x2 %0, %1, %2;" : "=l"(d) : "l"(a), "l"(b)); return d;
}
__device__ __forceinline__ u64 fma2(u64 a, u64 b, u64 c) {
    u64 d; asm("fma.rn.f32x2 %0, %1, %2, %3;" : "=l"(d) : "l"(a), "l"(b), "l"(c)); return d;
}

__device__ double g_partials[NWARPS];
__device__ unsigned int g_count = 0;

__global__ __launch_bounds__(32) void ssim_warp(const float* __restrict__ X,
                                                const float* __restrict__ Y,
                                                float* __restrict__ out) {
    const int wid = blockIdx.x;
    const int ch = wid >> 5;
    const int rem = wid & 31;
    const int band = rem >> 1;
    const int half = rem & 1;          // 0: cols 0-255 (+stub), 1: cols 256-511
    const int lane = threadIdx.x;
    const float* __restrict__ x = X + (size_t)ch * H * W;
    const float* __restrict__ y = Y + (size_t)ch * H * W;
    const int r0 = band * BH;
    const int rEnd = min(r0 + BH, OH);
    const int colbase = 256 * half + 4 * lane;  // group g at +128g (coalesced)
    const bool stubOn = (half == 0) && (lane < 2);  // stub cols 256 + 4*lane

    const u64 NEG1 = pk2(-1.0f, -1.0f);

    // packed column sums: sp[q][2g+h] = cols (4*lane + 2h, +1) of group g
    u64 sp[4][4];
    u64 st[4][2];  // stub sums (valid on lanes 0,1 of half 0)
#pragma unroll
    for (int q = 0; q < 4; q++) {
#pragma unroll
        for (int p = 0; p < 4; p++) sp[q][p] = 0ull;
        st[q][0] = st[q][1] = 0ull;
    }

#define ACCUM_PAIR(dst, xp, yp)                                               \
    {                                                                         \
        dst[0] = add2(dst[0], xp);                                            \
        dst[1] = add2(dst[1], yp);                                            \
        dst[2] = fma2(xp, xp, dst[2]);                                        \
        dst[3] = fma2(yp, yp, dst[3]);                                        \
        dst[4] = fma2(xp, yp, dst[4]);                                        \
    }

    // prologue: accumulate 7 input rows
#pragma unroll
    for (int rr = 0; rr < 7; rr++) {
        const size_t base = (size_t)(r0 + rr) * W + colbase;
#pragma unroll
        for (int g = 0; g < 2; g++) {
            const float4 a = *(const float4*)(x + base + 128 * g);
            const float4 b = *(const float4*)(y + base + 128 * g);
            const u64 x0 = pk2(a.x, a.y), x1 = pk2(a.z, a.w);
            const u64 y0 = pk2(b.x, b.y), y1 = pk2(b.z, b.w);
#pragma unroll
            for (int h = 0; h < 2; h++) {
                const u64 xp = h ? x1 : x0, yp = h ? y1 : y0;
                const int p = 2 * g + h;
                sp[0][p] = add2(sp[0][p], xp);
                sp[1][p] = add2(sp[1][p], yp);
                sp[2][p] = fma2(xp, xp, sp[2][p]);
                sp[2][p] = fma2(yp, yp, sp[2][p]);
                sp[3][p] = fma2(xp, yp, sp[3][p]);
            }
        }
        // stub cols 256+4*lane (lanes 0,1 only)
        float4 a = make_float4(0.f, 0.f, 0.f, 0.f), b = a;
        if (stubOn) {
            a = *(const float4*)(x + base + 256);
            b = *(const float4*)(y + base + 256);
        }
        const u64 x0 = pk2(a.x, a.y), x1 = pk2(a.z, a.w);
        const u64 y0 = pk2(b.x, b.y), y1 = pk2(b.z, b.w);
#pragma unroll
        for (int h = 0; h < 2; h++) {
            const u64 xp = h ? x1 : x0, yp = h ? y1 : y0;
            st[0][h] = add2(st[0][h], xp);
            st[1][h] = add2(st[1][h], yp);
            st[2][h] = fma2(xp, xp, st[2][h]);
            st[2][h] = fma2(yp, yp, st[2][h]);
            st[3][h] = fma2(xp, yp, st[3][h]);
        }
    }

    float acc = 0.0f;

    // prefetch buffers
    float4 pxn[2], pyn[2], pxo[2], pyo[2];       // regular: [group]
    float4 sxn, syn, sxo, syo;                   // stub

#define LOADP(rr)                                                             \
    {                                                                         \
        const size_t rn_ = (size_t)((rr) + 6) * W + colbase;                  \
        const size_t ro_ = (size_t)((rr) - 1) * W + colbase;                  \
        _Pragma("unroll")                                                     \
        for (int g = 0; g < 2; g++) {                                         \
            pxn[g] = *(const float4*)(x + rn_ + 128 * g);                     \
            pyn[g] = *(const float4*)(y + rn_ + 128 * g);                     \
            pxo[g] = *(const float4*)(x + ro_ + 128 * g);                     \
            pyo[g] = *(const float4*)(y + ro_ + 128 * g);                     \
        }                                                                     \
        if (stubOn) {                                                         \
            sxn = *(const float4*)(x + rn_ + 256);                            \
            syn = *(const float4*)(y + rn_ + 256);                            \
            sxo = *(const float4*)(x + ro_ + 256);                            \
            syo = *(const float4*)(y + ro_ + 256);                            \
        }                                                                     \
    }

#define ROLL_PAIR(arr, p, xn, yn, xo, yo)                                     \
    {                                                                         \
        arr[0][p] = add2(arr[0][p], fma2(xo, NEG1, xn));                      \
        arr[1][p] = add2(arr[1][p], fma2(yo, NEG1, yn));                      \
        u64 v_ = mul2(xo, xo);                                                \
        v_ = fma2(yo, yo, v_);                                                \
        arr[2][p] = fma2(xn, xn, arr[2][p]);                                  \
        arr[2][p] = fma2(yn, yn, arr[2][p]);                                  \
        arr[2][p] = fma2(v_, NEG1, arr[2][p]);                                \
        u64 m_ = mul2(xo, yo);                                                \
        arr[3][p] = fma2(xn, yn, arr[3][p]);                                  \
        arr[3][p] = fma2(m_, NEG1, arr[3][p]);                                \
    }

#define CONSUME()                                                             \
    {                                                                         \
        _Pragma("unroll")                                                     \
        for (int g = 0; g < 2; g++) {                                         \
            const u64 xn0 = pk2(pxn[g].x, pxn[g].y), xn1 = pk2(pxn[g].z, pxn[g].w); \
            const u64 yn0 = pk2(pyn[g].x, pyn[g].y), yn1 = pk2(pyn[g].z, pyn[g].w); \
            const u64 xo0 = pk2(pxo[g].x, pxo[g].y), xo1 = pk2(pxo[g].z, pxo[g].w); \
            const u64 yo0 = pk2(pyo[g].x, pyo[g].y), yo1 = pk2(pyo[g].z, pyo[g].w); \
            ROLL_PAIR(sp, 2 * g + 0, xn0, yn0, xo0, yo0);                     \
            ROLL_PAIR(sp, 2 * g + 1, xn1, yn1, xo1, yo1);                     \
        }                                                                     \
        if (half == 0) {                                                      \
            const u64 xn0 = pk2(sxn.x, sxn.y), xn1 = pk2(sxn.z, sxn.w);       \
            const u64 yn0 = pk2(syn.x, syn.y), yn1 = pk2(syn.z, syn.w);       \
            const u64 xo0 = pk2(sxo.x, sxo.y), xo1 = pk2(sxo.z, sxo.w);       \
            const u64 yo0 = pk2(syo.x, syo.y), yo1 = pk2(syo.z, syo.w);       \
            ROLL_PAIR(st, 0, xn0, yn0, xo0, yo0);                             \
            ROLL_PAIR(st, 1, xn1, yn1, xo1, yo1);                             \
        }                                                                     \
    }

#define PROCESS_ROW()                                                         \
    {                                                                         \
        /* prefixes per quantity per group: S0, P01, P012, S4 */              \
        float gS0[4][2], gP01[4][2], gP012[4][2], gS4[4][2];                  \
        float tS0[4], tP01[4], tP012[4], tS4[4]; /* stub prefixes */          \
        _Pragma("unroll")                                                     \
        for (int q = 0; q < 4; q++) {                                         \
            _Pragma("unroll")                                                 \
            for (int g = 0; g < 2; g++) {                                     \
                float e0, e1, e2, e3;                                         \
                upk2(sp[q][2 * g], e0, e1);                                   \
                upk2(sp[q][2 * g + 1], e2, e3);                               \
                gS0[q][g] = e0;                                               \
                gP01[q][g] = e0 + e1;                                         \
                gP012[q][g] = gP01[q][g] + e2;                                \
                gS4[q][g] = gP012[q][g] + e3;                                 \
            }                                                                 \
            float f0, f1, f2, f3;                                             \
            upk2(st[q][0], f0, f1);                                           \
            upk2(st[q][1], f2, f3);                                           \
            tS0[q] = f0;                                                      \
            tP01[q] = f0 + f1;                                                \
            tP012[q] = tP01[q] + f2;                                          \
            tS4[q] = tP012[q] + f3;                                           \
        }                                                                     \
        float w[4][8];                                                        \
        _Pragma("unroll")                                                     \
        for (int g = 0; g < 2; g++) {                                         \
            _Pragma("unroll")                                                 \
            for (int q = 0; q < 4; q++) {                                     \
                /* next-block prefixes: g=0 -> own g=1; g=1 -> stub */        \
                const float nS0   = g ? tS0[q]   : gS0[q][1];                 \
                const float nP01  = g ? tP01[q]  : gP01[q][1];                \
                const float nP012 = g ? tP012[q] : gP012[q][1];               \
                const float nS4   = g ? tS4[q]   : gS4[q][1];                 \
                const bool z1 = (lane == 0);                                  \
                const bool z2 = (lane < 2);                                   \
                const float pA1 = z1 ? nP012 : gP012[q][g];                   \
                const float pA2 = z1 ? nS4   : gS4[q][g];                     \
                const float pB1 = z2 ? nS0   : gS0[q][g];                     \
                const float pB2 = z2 ? nP01  : gP01[q][g];                    \
                const float A1 = __shfl_sync(0xffffffffu, pA1, (lane + 1) & 31); \
                const float A2 = __shfl_sync(0xffffffffu, pA2, (lane + 1) & 31); \
                const float B1 = __shfl_sync(0xffffffffu, pB1, (lane + 2) & 31); \
                const float B2 = __shfl_sync(0xffffffffu, pB2, (lane + 2) & 31); \
                const float S4v = gS4[q][g];                                  \
                w[q][4 * g + 0] = S4v + A1;                                   \
                w[q][4 * g + 1] = (S4v - gS0[q][g]) + A2;                     \
                w[q][4 * g + 2] = (S4v - gP01[q][g]) + A2 + B1;               \
                w[q][4 * g + 3] = (S4v - gP012[q][g]) + A2 + B2;              \
            }                                                                 \
        }                                                                     \
        float num[8], den[8];                                                 \
        _Pragma("unroll")                                                     \
        for (int k = 0; k < 8; k++) {                                         \
            const int g = k >> 2;                                             \
            const float Sx = w[0][k], Sy = w[1][k];                           \
            const float Szz = w[2][k], Sxy = w[3][k];                         \
            const float Pm = Sx * Sy;                                         \
            const float Q = fmaf(Sx, Sx, Sy * Sy);                            \
            const float A = fmaf(kA, Pm, C1f);                                \
            const float Cc = fmaf(kC, Q, C1f);                                \
            const float B = fmaf(kB1, Sxy, fmaf(-kB2, Pm, C2f));              \
            const float D = fmaf(kD1, Szz, fmaf(-kD2, Q, C2f));               \
            const bool valid = (half == 0) ||                                 \
                               (256 + 128 * g + 4 * lane + (k & 3) < OW);     \
            num[k] = valid ? A * B : 0.0f;                                    \
            den[k] = valid ? Cc * D : 1.0f;                                   \
        }                                                                     \
        /* single MUFU.RCP for 8 pixels */                                    \
        float pre[8];                                                         \
        pre[0] = 1.0f;                                                        \
        _Pragma("unroll")                                                     \
        for (int k = 1; k < 8; k++) pre[k] = pre[k - 1] * den[k - 1];         \
        const float rall = 1.0f / (pre[7] * den[7]);                          \
        float suf = 1.0f, contrib = 0.0f;                                     \
        _Pragma("unroll")                                                     \
        for (int k = 7; k >= 0; k--) {                                        \
            contrib = fmaf(num[k], pre[k] * suf, contrib);                    \
            suf *= den[k];                                                    \
        }                                                                     \
        acc = fmaf(contrib, rall, acc);                                       \
    }

    // software-pipelined main loop
    LOADP(r0 + 1);
    PROCESS_ROW();     // row r0 (sums valid from prologue)

    for (int r = r0 + 1; r < rEnd; r++) {
        CONSUME();
        if (r + 1 < rEnd) LOADP(r + 1);
        PROCESS_ROW();
    }

#undef LOADP
#undef CONSUME
#undef ROLL_PAIR
#undef ACCUM_PAIR
#undef PROCESS_ROW

    // warp tree-reduce (fixed order -> deterministic)
#pragma unroll
    for (int off = 16; off > 0; off >>= 1)
        acc += __shfl_down_sync(0xffffffffu, acc, off);

    int last = 0;
    if (lane == 0) {
        g_partials[wid] = (double)acc;
        __threadfence();
        const unsigned int c = atomicInc(&g_count, NWARPS - 1);  // wraps to 0
        last = (c == NWARPS - 1) ? 1 : 0;
    }
    last = __shfl_sync(0xffffffffu, last, 0);

    if (last) {
        const volatile double* vp = g_partials;
        double sd = 0.0;
        for (int i = lane; i < NWARPS; i += 32) sd += vp[i];
#pragma unroll
        for (int off = 16; off > 0; off >>= 1)
            sd += __shfl_down_sync(0xffffffffu, sd, off);
        if (lane == 0)
            out[0] = (float)(sd / ((double)CH * (double)OH * (double)OW));
    }
}

extern "C" void kernel_launch(void* const* d_in, const int* in_sizes, int n_in,
                              void* d_out, int out_size) {
    const float* x = (const float*)d_in[0];
    const float* y = (const float*)d_in[1];
    float* out = (float*)d_out;
    ssim_warp<<<NWARPS, 32>>>(x, y, out);
}